// round 17
// baseline (speedup 1.0000x reference)
#include <cuda_runtime.h>
#include <cuda_fp16.h>
#include <math.h>
#include <cstdint>

#define B_   8
#define C_   512
#define HW_  1024
#define M_   (B_*HW_)     // 8192 tokens
#define HID_ 2048
#define MC_  (M_*C_)      // 4194304
#define NQKV 1536

// ---------------- scratch (device globals; no allocation) ----------------
__device__ float g_O32[2*MC_];
__device__ __half g_Xh[2*MC_];
__device__ __half g_QKV[2*(size_t)M_*NQKV];
__device__ __half g_AO[2*MC_];
__device__ __half g_Eh[2*MC_];
__device__ __half g_Sh[2*MC_];
__device__ __half g_Fh[2*MC_];
__device__ __half g_H[2*(size_t)M_*HID_];
__device__ __half g_Wc[6291456];

// weight layout (halves):
// Wq0@0  Wk1@262144  Wv1@524288 | Wq1@786432 Wk0@1048576 Wv0@1310720
// Wo0@1572864 Wo1@1835008 | W1_0@2097152 W2_0@3145728 W1_1@4194304 W2_1@5242880
// Wq pre-scaled by 0.125*log2(e).

// ==================== helpers ====================
__device__ __forceinline__ uint32_t smem_u32(const void* p) {
  uint32_t a;
  asm("{ .reg .u64 t; cvta.to.shared.u64 t, %1; cvt.u32.u64 %0, t; }" : "=r"(a) : "l"(p));
  return a;
}
__device__ __forceinline__ void ldm_x4(uint32_t* r, uint32_t addr) {
  asm volatile("ldmatrix.sync.aligned.m8n8.x4.shared.b16 {%0,%1,%2,%3}, [%4];"
               : "=r"(r[0]), "=r"(r[1]), "=r"(r[2]), "=r"(r[3]) : "r"(addr));
}
__device__ __forceinline__ void ldm_x4_t(uint32_t* r, uint32_t addr) {
  asm volatile("ldmatrix.sync.aligned.m8n8.x4.trans.shared.b16 {%0,%1,%2,%3}, [%4];"
               : "=r"(r[0]), "=r"(r[1]), "=r"(r[2]), "=r"(r[3]) : "r"(addr));
}
__device__ __forceinline__ void mma16816(float* d, const uint32_t* a, const uint32_t* b) {
  asm volatile("mma.sync.aligned.m16n8k16.row.col.f32.f16.f16.f32 "
               "{%0,%1,%2,%3}, {%4,%5,%6,%7}, {%8,%9}, {%0,%1,%2,%3};"
               : "+f"(d[0]), "+f"(d[1]), "+f"(d[2]), "+f"(d[3])
               : "r"(a[0]), "r"(a[1]), "r"(a[2]), "r"(a[3]), "r"(b[0]), "r"(b[1]));
}
__device__ __forceinline__ void cp16(uint32_t saddr, const void* g) {
  asm volatile("cp.async.cg.shared.global [%0], [%1], 16;" :: "r"(saddr), "l"(g));
}
__device__ __forceinline__ void cp_commit() { asm volatile("cp.async.commit_group;" ::: "memory"); }
template <int N>
__device__ __forceinline__ void cp_wait() { asm volatile("cp.async.wait_group %0;" :: "n"(N) : "memory"); }

__device__ __forceinline__ uint32_t pk_h2(__half a, __half b) {
  __half2 t; t.x = a; t.y = b;
  return *(uint32_t*)&t;
}
__device__ __forceinline__ uint32_t pk_f2h(float a, float b) {
  return pk_h2(__float2half_rn(a), __float2half_rn(b));
}
__device__ __forceinline__ float2 h2f2(uint32_t u) {
  __half2 h = *(__half2*)&u;
  return __half22float2(h);
}
__device__ __forceinline__ float ex2f(float x) {
  float r;
  asm("ex2.approx.f32 %0, %1;" : "=f"(r) : "f"(x));
  return r;
}
__device__ __forceinline__ float gelu_exact(float v) {
  return 0.5f * v * (1.0f + erff(v * 0.70710678118654752f));
}

// ==================== mma.sync GEMM: C[M,N] = A@W^T (+bias,+GELU) ====================
// CTA 128(M) x 256(N), 8 warps (2m x 4n) of 64x64 tiles, 256 threads, occ 1,
// 4-stage cp.async pipeline. Bytes/KMAC = 23.4 (vs 31.3 at 128x128) to relieve
// the LDGSTS dispatch floor (~1 op/cyc/SM).
#define BKC 32
#define TSTRIDE 40
#define TILE_A (128*TSTRIDE*2)       // 10240 B
#define TILE_W (256*TSTRIDE*2)       // 20480 B
#define CHUNK_B (TILE_A + TILE_W)    // 30720 B
#define GT_SMEM (4*CHUNK_B)          // 122880 B (occ 1)
#define GT_THR 256

struct GP {
  const __half* A[2]; const __half* W[2]; const float* bias[2];
  float* Co[2]; __half* Ch[2];
};

// OUT: 0 = fp32, 2 = single fp16
template <int DO_GELU, int OUT>
__global__ void __launch_bounds__(GT_THR, 1)
gemm_mma(GP p, int N, int K) {
  extern __shared__ char smem[];
  uint32_t sbase = smem_u32(smem);
  int tid = threadIdx.x, lane = tid & 31, warp = tid >> 5;
  int warp_m = warp & 1, warp_n = warp >> 1;   // 2m x 4n of 64x64
  int bn = blockIdx.x, bm = blockIdx.y, br = blockIdx.z;

  const __half* srcA = p.A[br] + (size_t)bm * 128 * K;
  const __half* srcW = p.W[br] + (size_t)bn * 256 * K;

  auto load_chunk = [&](int buf, int kt) {
    uint32_t bb = sbase + buf * CHUNK_B;
    // A: 128 rows x 64 B = 512 cp16 (2/thread)
#pragma unroll
    for (int i = 0; i < 2; i++) {
      int idx = i * GT_THR + tid;
      int row = idx >> 2, seg = idx & 3;
      cp16(bb + row * (TSTRIDE * 2) + seg * 16, srcA + (size_t)row * K + kt + seg * 8);
    }
    // W: 256 rows x 64 B = 1024 cp16 (4/thread)
#pragma unroll
    for (int i = 0; i < 4; i++) {
      int idx = i * GT_THR + tid;
      int row = idx >> 2, seg = idx & 3;
      cp16(bb + TILE_A + row * (TSTRIDE * 2) + seg * 16, srcW + (size_t)row * K + kt + seg * 8);
    }
  };

  float acc[4][8][4];
#pragma unroll
  for (int t = 0; t < 4; t++)
#pragma unroll
    for (int n = 0; n < 8; n++)
#pragma unroll
      for (int j = 0; j < 4; j++) acc[t][n][j] = 0.f;

  int nk = K / BKC;
#pragma unroll
  for (int s = 0; s < 3; s++) {
    if (s < nk) load_chunk(s, s * BKC);
    cp_commit();
  }

  for (int i = 0; i < nk; i++) {
    cp_wait<2>();
    __syncthreads();
    if (i + 3 < nk) load_chunk((i + 3) & 3, (i + 3) * BKC);
    cp_commit();

    uint32_t bb = sbase + (i & 3) * CHUNK_B;
    uint32_t abase = bb, wbase = bb + TILE_A;

#pragma unroll
    for (int ks = 0; ks < 2; ks++) {
      uint32_t afr[4][4];
#pragma unroll
      for (int t = 0; t < 4; t++) {
        int row = warp_m * 64 + t * 16 + (lane & 15);
        uint32_t off = row * (TSTRIDE * 2) + ks * 32 + (lane >> 4) * 16;
        ldm_x4(afr[t], abase + off);
      }
      uint32_t bfr[8][2];
#pragma unroll
      for (int pq = 0; pq < 4; pq++) {
        int g = lane >> 3;
        int row = warp_n * 64 + pq * 16 + ((g >> 1) << 3) + (lane & 7);
        uint32_t off = row * (TSTRIDE * 2) + (g & 1) * 16 + ks * 32;
        uint32_t r4[4];
        ldm_x4(r4, wbase + off);
        bfr[pq * 2][0] = r4[0]; bfr[pq * 2][1] = r4[1];
        bfr[pq * 2 + 1][0] = r4[2]; bfr[pq * 2 + 1][1] = r4[3];
      }
#pragma unroll
      for (int t = 0; t < 4; t++)
#pragma unroll
        for (int n = 0; n < 8; n++)
          mma16816(acc[t][n], afr[t], bfr[n]);
    }
  }

  int q = lane >> 2, rr = lane & 3;
  const float* bias = p.bias[br];
#pragma unroll
  for (int t = 0; t < 4; t++) {
    int row0 = bm * 128 + warp_m * 64 + t * 16 + q;
#pragma unroll
    for (int n = 0; n < 8; n++) {
      int col = bn * 256 + warp_n * 64 + n * 8 + rr * 2;
      float bx = bias ? bias[col] : 0.f;
      float by = bias ? bias[col + 1] : 0.f;
      float o0x = acc[t][n][0] + bx, o0y = acc[t][n][1] + by;
      float o1x = acc[t][n][2] + bx, o1y = acc[t][n][3] + by;
      if (DO_GELU) {
        o0x = gelu_exact(o0x); o0y = gelu_exact(o0y);
        o1x = gelu_exact(o1x); o1y = gelu_exact(o1y);
      }
      if (OUT == 2) {
        *(uint32_t*)(p.Ch[br] + (size_t)row0 * N + col) = pk_f2h(o0x, o0y);
        *(uint32_t*)(p.Ch[br] + (size_t)(row0 + 8) * N + col) = pk_f2h(o1x, o1y);
      } else {
        *(float2*)(p.Co[br] + (size_t)row0 * N + col) = make_float2(o0x, o0y);
        *(float2*)(p.Co[br] + (size_t)(row0 + 8) * N + col) = make_float2(o1x, o1y);
      }
    }
  }
}

// ==================== flash attention, no-max softmax (unchanged R15) ====================
#define ASTRIDE 144
#define KVT (64*ASTRIDE)
#define ABUF (2*KVT)
#define QOFF (3*ABUF)
#define ATT_SMEM (3*ABUF + 18432)

struct AP { const __half* Q[2]; const __half* KV[2]; __half* O[2]; };

__global__ void __launch_bounds__(256, 2) attn_mma(AP p) {
  extern __shared__ char smraw[];
  uint32_t sb = smem_u32(smraw);
  int qt = blockIdx.x, h = blockIdx.y;
  int br = blockIdx.z >> 3, b = blockIdx.z & 7;
  int tid = threadIdx.x, warp = tid >> 5, lane = tid & 31;
  int gid = lane >> 2, tig = lane & 3;
  const __half* KV = p.KV[br];

  auto kvload = [&](int buf, int kt) {
    uint32_t bb = sb + buf * ABUF;
    size_t rb = (size_t)(b * HW_ + kt * 64);
#pragma unroll
    for (int i = 0; i < 2; i++) {
      int idx = i * 256 + tid;
      int row = idx >> 3, seg = idx & 7;
      size_t g = (rb + row) * NQKV + h * 64 + seg * 8;
      uint32_t so = row * ASTRIDE + seg * 16;
      cp16(bb + so, KV + g);
      cp16(bb + KVT + so, KV + g + 512);
    }
  };

  {
    const __half* qh = p.Q[br] + ((size_t)(b * HW_ + qt * 128)) * NQKV + h * 64;
#pragma unroll
    for (int i = 0; i < 4; i++) {
      int idx = i * 256 + tid;
      int row = idx >> 3, seg = idx & 7;
      cp16(sb + QOFF + row * ASTRIDE + seg * 16, qh + (size_t)row * NQKV + seg * 8);
    }
  }
  kvload(0, 0);
  cp_commit();
  kvload(1, 1);
  cp_commit();

  uint32_t qf[4][4];
  float l0 = 0.f, l1 = 0.f;
  float oacc[8][4];
#pragma unroll
  for (int d = 0; d < 8; d++)
#pragma unroll
    for (int j = 0; j < 4; j++) oacc[d][j] = 0.f;

  int g8 = lane >> 3;
  uint32_t boff_k = (((g8 >> 1) << 3) + (lane & 7)) * ASTRIDE + (g8 & 1) * 16;
  uint32_t boff_v = (8 * (g8 & 1) + (lane & 7)) * ASTRIDE + 16 * (g8 >> 1);

  for (int kt = 0; kt < 16; kt++) {
    if (kt < 15) cp_wait<1>(); else cp_wait<0>();
    __syncthreads();
    if (kt == 0) {
      uint32_t rowoff = (warp * 16 + (lane & 15)) * ASTRIDE + (lane >> 4) * 16;
#pragma unroll
      for (int t = 0; t < 4; t++)
        ldm_x4(qf[t], sb + QOFF + rowoff + t * 32);
    }
    if (kt + 2 < 16) {
      kvload((kt + 2) % 3, kt + 2);
      cp_commit();
    }

    uint32_t bb = sb + (kt % 3) * ABUF;
    float sacc[8][4];
#pragma unroll
    for (int j = 0; j < 8; j++)
#pragma unroll
      for (int r = 0; r < 4; r++) sacc[j][r] = 0.f;

#pragma unroll
    for (int t = 0; t < 4; t++) {
#pragma unroll
      for (int pq = 0; pq < 4; pq++) {
        uint32_t off = pq * 16 * ASTRIDE + boff_k + t * 32;
        uint32_t kh[4];
        ldm_x4(kh, bb + off);
        mma16816(sacc[2 * pq], qf[t], kh);
        mma16816(sacc[2 * pq + 1], qf[t], kh + 2);
      }
    }

#pragma unroll
    for (int j = 0; j < 8; j++) {
      sacc[j][0] = ex2f(sacc[j][0]);
      sacc[j][1] = ex2f(sacc[j][1]);
      sacc[j][2] = ex2f(sacc[j][2]);
      sacc[j][3] = ex2f(sacc[j][3]);
      l0 += sacc[j][0] + sacc[j][1];
      l1 += sacc[j][2] + sacc[j][3];
    }

#pragma unroll
    for (int t = 0; t < 4; t++) {
      uint32_t ah[4];
      ah[0] = pk_f2h(sacc[2 * t][0], sacc[2 * t][1]);
      ah[1] = pk_f2h(sacc[2 * t][2], sacc[2 * t][3]);
      ah[2] = pk_f2h(sacc[2 * t + 1][0], sacc[2 * t + 1][1]);
      ah[3] = pk_f2h(sacc[2 * t + 1][2], sacc[2 * t + 1][3]);
#pragma unroll
      for (int pd = 0; pd < 4; pd++) {
        uint32_t off = t * 16 * ASTRIDE + boff_v + pd * 32;
        uint32_t vh[4];
        ldm_x4_t(vh, bb + KVT + off);
        mma16816(oacc[2 * pd], ah, vh);
        mma16816(oacc[2 * pd + 1], ah, vh + 2);
      }
    }
  }

  l0 += __shfl_xor_sync(0xffffffffu, l0, 1);
  l0 += __shfl_xor_sync(0xffffffffu, l0, 2);
  l1 += __shfl_xor_sync(0xffffffffu, l1, 1);
  l1 += __shfl_xor_sync(0xffffffffu, l1, 2);
  float inv0 = 1.f / l0, inv1 = 1.f / l1;

  __half* O = p.O[br];
  size_t q0 = (size_t)(b * HW_ + qt * 128 + warp * 16 + gid);
  size_t q1 = q0 + 8;
#pragma unroll
  for (int d = 0; d < 8; d++) {
    int col = h * 64 + d * 8 + 2 * tig;
    *(uint32_t*)(O + q0 * C_ + col) = pk_f2h(oacc[d][0] * inv0, oacc[d][1] * inv0);
    *(uint32_t*)(O + q1 * C_ + col) = pk_f2h(oacc[d][2] * inv1, oacc[d][3] * inv1);
  }
}

// ---------------- one-shot weight conversion (Wq pre-scaled) ----------------
struct W12 { const float* s[12]; };
__global__ void __launch_bounds__(256) cvt_weights(W12 p, __half* __restrict__ dst) {
  long e = (long)blockIdx.x * 1024 + (long)threadIdx.x * 4;
  int mid; long off;
  if (e < 2097152) {
    mid = (int)(e >> 18); off = e & 262143;
  } else {
    long e2 = e - 2097152;
    mid = 8 + (int)(e2 >> 20); off = e2 & 1048575;
  }
  long base; float scl = 1.f;
  const float QSCL = 0.125f * 1.4426950408889634f;
  switch (mid) {
    case 0:  base = 0;       scl = QSCL; break;
    case 1:  base = 1048576; break;
    case 2:  base = 1310720; break;
    case 3:  base = 1572864; break;
    case 4:  base = 786432;  scl = QSCL; break;
    case 5:  base = 262144;  break;
    case 6:  base = 524288;  break;
    case 7:  base = 1835008; break;
    case 8:  base = 2097152; break;
    case 9:  base = 3145728; break;
    case 10: base = 4194304; break;
    default: base = 5242880; break;
  }
  float4 v = *(const float4*)(p.s[mid] + off);
  *(uint32_t*)(dst + base + off) = pk_f2h(v.x * scl, v.y * scl);
  *(uint32_t*)(dst + base + off + 2) = pk_f2h(v.z * scl, v.w * scl);
}

// ---------------- input transpose + fp16 cast ----------------
struct TP { const float* in[2]; __half* oh[2]; };
__global__ void __launch_bounds__(256) btrsp_in(TP p) {
  __shared__ float t[32][33];
  int br = blockIdx.z >> 3, b = blockIdx.z & 7;
  const float* pin = p.in[br] + (size_t)b * C_ * HW_;
  size_t ob = (size_t)b * HW_ * C_;
  int c0 = blockIdx.x * 32, r0 = blockIdx.y * 32;
  int x = threadIdx.x, y = threadIdx.y;
#pragma unroll
  for (int j = 0; j < 32; j += 8)
    t[y + j][x] = pin[(size_t)(r0 + y + j) * HW_ + c0 + x];
  __syncthreads();
#pragma unroll
  for (int j = 0; j < 32; j += 8)
    p.oh[br][ob + (size_t)(c0 + y + j) * C_ + r0 + x] = __float2half_rn(t[x][y + j]);
}

// ---------------- output transpose ----------------
struct OP { const float* in[2]; float* out; };
__global__ void __launch_bounds__(256) btrsp_out(OP p) {
  __shared__ float t[32][33];
  int br = blockIdx.z >> 3, b = blockIdx.z & 7;
  const float* pin = p.in[br] + (size_t)b * HW_ * C_;
  float* pout = p.out + (size_t)br * MC_ + (size_t)b * C_ * HW_;
  int c0 = blockIdx.x * 32, r0 = blockIdx.y * 32;
  int x = threadIdx.x, y = threadIdx.y;
#pragma unroll
  for (int j = 0; j < 32; j += 8)
    t[y + j][x] = pin[(size_t)(r0 + y + j) * C_ + c0 + x];
  __syncthreads();
#pragma unroll
  for (int j = 0; j < 32; j += 8)
    pout[(size_t)(c0 + y + j) * HW_ + r0 + x] = t[x][y + j];
}

// ---------------- LayerNorm(X + Y) over C, fp16 inputs ----------------
struct LP {
  const __half* X[2]; const __half* Y[2]; const float* w[2]; const float* b[2];
  float* out[2]; __half* oh[2];
};
template <int OUT32>
__global__ void __launch_bounds__(256) ln_res(LP p) {
  int br = blockIdx.y;
  int row = blockIdx.x * 8 + (threadIdx.x >> 5);
  int lane = threadIdx.x & 31;
  const __half* px = p.X[br] + (size_t)row * C_;
  const __half* py = p.Y[br] + (size_t)row * C_;
  const float* w = p.w[br];
  const float* bb = p.b[br];
  float2 v[8];
  float s = 0.f;
#pragma unroll
  for (int i = 0; i < 8; i++) {
    float2 a = h2f2(*(const uint32_t*)&px[2 * lane + 64 * i]);
    float2 c = h2f2(*(const uint32_t*)&py[2 * lane + 64 * i]);
    v[i] = make_float2(a.x + c.x, a.y + c.y);
    s += v[i].x + v[i].y;
  }
#pragma unroll
  for (int off = 16; off > 0; off >>= 1) s += __shfl_xor_sync(0xffffffffu, s, off);
  float mean = s * (1.0f / C_);
  float s2 = 0.f;
#pragma unroll
  for (int i = 0; i < 8; i++) {
    float dx = v[i].x - mean, dy = v[i].y - mean;
    s2 += dx * dx + dy * dy;
  }
#pragma unroll
  for (int off = 16; off > 0; off >>= 1) s2 += __shfl_xor_sync(0xffffffffu, s2, off);
  float inv = rsqrtf(s2 * (1.0f / C_) + 1e-6f);
#pragma unroll
  for (int i = 0; i < 8; i++) {
    int c = 2 * lane + 64 * i;
    float ox = (v[i].x - mean) * inv * w[c] + bb[c];
    float oy = (v[i].y - mean) * inv * w[c + 1] + bb[c + 1];
    if (OUT32)
      *(float2*)(p.out[br] + (size_t)row * C_ + c) = make_float2(ox, oy);
    else
      *(uint32_t*)(p.oh[br] + (size_t)row * C_ + c) = pk_f2h(ox, oy);
  }
}

// ---------------- launch ----------------
extern "C" void kernel_launch(void* const* d_in, const int* in_sizes, int n_in,
                              void* d_out, int out_size) {
  (void)in_sizes; (void)n_in; (void)out_size;
  const float* spatial = (const float*)d_in[0];
  const float* freq    = (const float*)d_in[1];
  const float* Wq[2] = {(const float*)d_in[2],  (const float*)d_in[7]};
  const float* Wk[2] = {(const float*)d_in[3],  (const float*)d_in[8]};
  const float* Wv[2] = {(const float*)d_in[4],  (const float*)d_in[9]};
  const float* Wo[2] = {(const float*)d_in[5],  (const float*)d_in[10]};
  const float* bo[2] = {(const float*)d_in[6],  (const float*)d_in[11]};
  const float* n1w[2] = {(const float*)d_in[12], (const float*)d_in[16]};
  const float* n1b[2] = {(const float*)d_in[13], (const float*)d_in[17]};
  const float* n2w[2] = {(const float*)d_in[14], (const float*)d_in[18]};
  const float* n2b[2] = {(const float*)d_in[15], (const float*)d_in[19]};
  const float* W1[2] = {(const float*)d_in[20], (const float*)d_in[24]};
  const float* b1[2] = {(const float*)d_in[21], (const float*)d_in[25]};
  const float* W2[2] = {(const float*)d_in[22], (const float*)d_in[26]};
  const float* b2[2] = {(const float*)d_in[23], (const float*)d_in[27]};
  float* out = (float*)d_out;

  float* O32;
  __half *Xh, *QKV, *AO, *Eh, *Sh, *Fh, *H, *Wc;
  cudaGetSymbolAddress((void**)&O32, g_O32);
  cudaGetSymbolAddress((void**)&Xh, g_Xh);
  cudaGetSymbolAddress((void**)&QKV, g_QKV);
  cudaGetSymbolAddress((void**)&AO, g_AO);
  cudaGetSymbolAddress((void**)&Eh, g_Eh);
  cudaGetSymbolAddress((void**)&Sh, g_Sh);
  cudaGetSymbolAddress((void**)&Fh, g_Fh);
  cudaGetSymbolAddress((void**)&H, g_H);
  cudaGetSymbolAddress((void**)&Wc, g_Wc);

  cudaFuncSetAttribute(attn_mma, cudaFuncAttributeMaxDynamicSharedMemorySize, ATT_SMEM);
  cudaFuncSetAttribute(gemm_mma<0, 0>, cudaFuncAttributeMaxDynamicSharedMemorySize, GT_SMEM);
  cudaFuncSetAttribute(gemm_mma<0, 2>, cudaFuncAttributeMaxDynamicSharedMemorySize, GT_SMEM);
  cudaFuncSetAttribute(gemm_mma<1, 2>, cudaFuncAttributeMaxDynamicSharedMemorySize, GT_SMEM);

  dim3 tp_threads(32, 8);
  const size_t QKVSZ = (size_t)M_ * NQKV;

  {
    TP p;
    p.in[0] = spatial; p.in[1] = freq;
    p.oh[0] = Xh; p.oh[1] = Xh + MC_;
    btrsp_in<<<dim3(HW_ / 32, C_ / 32, 16), tp_threads>>>(p);
  }
  {
    W12 p;
    p.s[0] = Wq[0]; p.s[1] = Wk[0]; p.s[2] = Wv[0]; p.s[3] = Wo[0];
    p.s[4] = Wq[1]; p.s[5] = Wk[1]; p.s[6] = Wv[1]; p.s[7] = Wo[1];
    p.s[8] = W1[0]; p.s[9] = W2[0]; p.s[10] = W1[1]; p.s[11] = W2[1];
    cvt_weights<<<6144, 256>>>(p, Wc);
  }

  // QKV fused: group0 (A=Xs) -> [Q0|K1|V1], group1 (A=Xf) -> [Q1|K0|V0]
  {
    GP p{};
    p.A[0] = Xh; p.A[1] = Xh + MC_;
    p.W[0] = Wc; p.W[1] = Wc + 786432;
    p.Ch[0] = QKV; p.Ch[1] = QKV + QKVSZ;
    gemm_mma<0, 2><<<dim3(6, 64, 2), GT_THR, GT_SMEM>>>(p, NQKV, C_);
  }
  // attention
  {
    AP p;
    p.Q[0] = QKV;          p.KV[0] = QKV + QKVSZ + 512;
    p.Q[1] = QKV + QKVSZ;  p.KV[1] = QKV + 512;
    p.O[0] = AO; p.O[1] = AO + MC_;
    attn_mma<<<dim3(8, 8, 16), 256, ATT_SMEM>>>(p);
  }
  // E = AO Wo^T + bo (fp16 out)
  {
    GP p{};
    p.A[0] = AO; p.A[1] = AO + MC_;
    p.W[0] = Wc + 1572864; p.W[1] = Wc + 1835008;
    p.bias[0] = bo[0]; p.bias[1] = bo[1];
    p.Ch[0] = Eh; p.Ch[1] = Eh + MC_;
    gemm_mma<0, 2><<<dim3(2, 64, 2), GT_THR, GT_SMEM>>>(p, C_, C_);
  }
  // S = LN(Xq + E)
  {
    LP p{};
    p.X[0] = Xh; p.X[1] = Xh + MC_;
    p.Y[0] = Eh; p.Y[1] = Eh + MC_;
    p.w[0] = n1w[0]; p.w[1] = n1w[1];
    p.b[0] = n1b[0]; p.b[1] = n1b[1];
    p.oh[0] = Sh; p.oh[1] = Sh + MC_;
    ln_res<0><<<dim3(M_ / 8, 2), 256>>>(p);
  }
  // H = gelu(S W1^T + b1)
  {
    GP p{};
    p.A[0] = Sh; p.A[1] = Sh + MC_;
    p.W[0] = Wc + 2097152; p.W[1] = Wc + 4194304;
    p.bias[0] = b1[0]; p.bias[1] = b1[1];
    p.Ch[0] = H; p.Ch[1] = H + (size_t)M_ * HID_;
    gemm_mma<1, 2><<<dim3(8, 64, 2), GT_THR, GT_SMEM>>>(p, HID_, C_);
  }
  // F = H W2^T + b2 (fp16 out)
  {
    GP p{};
    p.A[0] = H; p.A[1] = H + (size_t)M_ * HID_;
    p.W[0] = Wc + 3145728; p.W[1] = Wc + 5242880;
    p.bias[0] = b2[0]; p.bias[1] = b2[1];
    p.Ch[0] = Fh; p.Ch[1] = Fh + MC_;
    gemm_mma<0, 2><<<dim3(2, 64, 2), GT_THR, GT_SMEM>>>(p, C_, HID_);
  }
  // O = LN(S + F) (fp32 out)
  {
    LP p{};
    p.X[0] = Sh; p.X[1] = Sh + MC_;
    p.Y[0] = Fh; p.Y[1] = Fh + MC_;
    p.w[0] = n2w[0]; p.w[1] = n2w[1];
    p.b[0] = n2b[0]; p.b[1] = n2b[1];
    p.out[0] = O32; p.out[1] = O32 + MC_;
    ln_res<1><<<dim3(M_ / 8, 2), 256>>>(p);
  }
  {
    OP p;
    p.in[0] = O32; p.in[1] = O32 + MC_;
    p.out = out;
    btrsp_out<<<dim3(C_ / 32, HW_ / 32, 16), tp_threads>>>(p);
  }
}